// round 6
// baseline (speedup 1.0000x reference)
#include <cuda_runtime.h>
#include <cuda_bf16.h>

// LeakyAvg: out[b,h,t,d] = sum_{s<=t} exp(-beta_h*(t-s)) * k[b,h,s,d]
//  == linear recurrence y[t] = a*y[t-1] + k[t], a = exp(-beta_h) <= e^-0.5.
// Influence beyond lag 32 is a^32 <= e^-16 ~ 1.1e-7 (rel), far below the 1e-3
// gate -> chunks of T computed independently with a 32-step warm-up.
//
// R3: occ 10%, DRAM 22% -> latency-bound.  R5 (CHUNK=32): occ 36.8% (exactly
// the grid-imposed cap), DRAM 28.5% -> still stream-starved; occupancy was
// grid-limited, not resource-limited (regs=32).  R6: CHUNK=16 -> 8192 streams
// (~55 warps/SM, ~86% occ cap). Read amp 3x, but the input is L2-resident
// (33.5 MB vs 126 MB L2) and L2 was only 29% busy -> extra reads are free.
//
// One WARP owns one (b,h,chunk); each lane owns 2 dims (float2); a warp
// reads/writes the full 64-float row (256 B) per timestep, coalesced.

namespace {
constexpr int NH = 16;
constexpr int T  = 2048;
constexpr int HS = 64;
constexpr int CHUNK = 16;           // emitted timesteps per warp
constexpr int WARM  = 32;           // warm-up timesteps (discarded)
constexpr int WARPS_PER_BLOCK = 4;  // adjacent chunks
}

__global__ __launch_bounds__(32 * WARPS_PER_BLOCK)
void leaky_avg_scan_kernel(const float* __restrict__ k,
                           const float* __restrict__ lkb,
                           float* __restrict__ out)
{
    const int warp  = threadIdx.x >> 5;
    const int lane  = threadIdx.x & 31;
    const int chunk = blockIdx.x * WARPS_PER_BLOCK + warp;  // 0 .. T/CHUNK-1
    const int h     = blockIdx.y;
    const int b     = blockIdx.z;

    const float beta = fabsf(lkb[h]) * 10.0f;
    const float a = expf(-beta);

    const int t0 = chunk * CHUNK;
    const int ts = (t0 >= WARM) ? (t0 - WARM) : 0;
    const int nwarm = t0 - ts;   // 0, 16, or 32

    const size_t row = ((size_t)(b * NH + h)) * T;
    constexpr int STRIDE2 = HS / 2;  // float2 elements per timestep row

    float2 y = make_float2(0.0f, 0.0f);

    // Warm-up: establish the state at t0-1 (exact to fp32; tail term < e^-16).
    {
        const float2* wp = reinterpret_cast<const float2*>(
            k + (row + ts) * HS) + lane;
        #pragma unroll 8
        for (int i = 0; i < nwarm; ++i) {
            float2 kv = wp[i * STRIDE2];
            y.x = fmaf(a, y.x, kv.x);
            y.y = fmaf(a, y.y, kv.y);
        }
    }

    const float2* kp = reinterpret_cast<const float2*>(k + (row + t0) * HS) + lane;
    float2* op = reinterpret_cast<float2*>(out + (row + t0) * HS) + lane;

    // Emit loop: fully unrolled (16 iterations).
    #pragma unroll
    for (int i = 0; i < CHUNK; ++i) {
        float2 kv = kp[i * STRIDE2];
        y.x = fmaf(a, y.x, kv.x);
        y.y = fmaf(a, y.y, kv.y);
        op[i * STRIDE2] = y;
    }
}

extern "C" void kernel_launch(void* const* d_in, const int* in_sizes, int n_in,
                              void* d_out, int out_size)
{
    const float* k   = (const float*)d_in[0];
    const float* lkb = (const float*)d_in[1];
    float* out = (float*)d_out;

    const int B = in_sizes[0] / (NH * T * HS);   // 4 for this problem

    dim3 grid(T / (CHUNK * WARPS_PER_BLOCK), NH, B);  // (32, 16, 4) = 2048 blocks
    dim3 block(32 * WARPS_PER_BLOCK);                 // 128 threads
    leaky_avg_scan_kernel<<<grid, block>>>(k, lkb, out);
}